// round 2
// baseline (speedup 1.0000x reference)
#include <cuda_runtime.h>
#include <cuda_bf16.h>
#include <math.h>

#define N_ATOMS 10000
#define N_EDGES 250000
#define F_DIM   128
#define F3      384
#define N_RBF   20
#define CUTOFF  5.0f
#define EPSV    1e-8f

// ---------------- scratch (device globals; no allocation allowed) ----------------
__device__ float g_Wij[(size_t)N_EDGES * F3];     // 384 MB
__device__ float g_dir[(size_t)N_EDGES * 3];
__device__ float g_q   [N_ATOMS * F_DIM];
__device__ float g_mu  [N_ATOMS * 3 * F_DIM];
__device__ float g_h   [N_ATOMS * F_DIM];
__device__ float g_x   [N_ATOMS * F3];
__device__ float g_dq  [N_ATOMS * F_DIM];
__device__ float g_dmu [N_ATOMS * 3 * F_DIM];
__device__ float g_mumix[N_ATOMS * 3 * 2 * F_DIM];
__device__ float g_ctx [N_ATOMS * 2 * F_DIM];
__device__ float g_hm  [N_ATOMS * F_DIM];
__device__ float g_xm  [N_ATOMS * F3];

// packed f32x2 helpers (FFMA2 — PTX-only, doubles fp32 FMA throughput)
#define FMA_F32X2(acc, a, b) \
    asm("fma.rn.f32x2 %0, %1, %2, %0;" : "+l"(acc) : "l"(a), "l"(b))
#define PACK_DUP(out, x) \
    asm("mov.b64 %0, {%1, %1};" : "=l"(out) : "r"(x))
#define UNPACK2(lo, hi, in) \
    asm("mov.b64 {%0, %1}, %2;" : "=r"(lo), "=r"(hi) : "l"(in))

// ---------------- edge precompute: dir + Wij ----------------
__global__ void edge_pre(const float* __restrict__ R,
                         const int* __restrict__ idx_i,
                         const int* __restrict__ idx_j,
                         const float* __restrict__ offs,
                         const float* __restrict__ filt_W,
                         const float* __restrict__ filt_b) {
    long e = blockIdx.x;
    int t = threadIdx.x;  // 128 threads
    __shared__ float s_phi[N_RBF];

    // geometry computed redundantly by all threads (broadcast loads)
    int i = idx_i[e], j = idx_j[e];
    float rx = R[j*3+0] - R[i*3+0] + offs[e*3+0];
    float ry = R[j*3+1] - R[i*3+1] + offs[e*3+1];
    float rz = R[j*3+2] - R[i*3+2] + offs[e*3+2];
    float d = sqrtf(rx*rx + ry*ry + rz*rz);
    float inv = 1.0f / d;
    float fc = (d < CUTOFF) ? 0.5f * (cosf(d * (float)(M_PI / 5.0)) + 1.0f) : 0.0f;

    if (t < N_RBF) {
        const float spacing = CUTOFF / (float)(N_RBF - 1);
        const float coeff = -0.5f / (spacing * spacing);
        float dd = d - (float)t * spacing;
        s_phi[t] = expf(coeff * dd * dd);
    }
    __syncthreads();

    #pragma unroll
    for (int p = 0; p < 3; ++p) {
        int c = t + p * F_DIM;
        float acc = filt_b[c];
        #pragma unroll
        for (int r = 0; r < N_RBF; ++r)
            acc += s_phi[r] * filt_W[r * F3 + c];
        g_Wij[e * F3 + c] = acc * fc;
    }
    if (t < 3) g_dir[e * 3 + t] = (t == 0 ? rx : (t == 1 ? ry : rz)) * inv;
}

// ---------------- init: q = emb[Z], mu = 0 ----------------
__global__ void init_atoms(const int* __restrict__ Z, const float* __restrict__ emb) {
    int n = blockIdx.x, t = threadIdx.x;
    int z = Z[n];
    g_q[n * F_DIM + t] = emb[z * F_DIM + t];
    #pragma unroll
    for (int a = 0; a < 3; ++a) g_mu[(n * 3 + a) * F_DIM + t] = 0.0f;
}

// ---------------- SGEMM: C = act(A[M,K] @ B[K,N] + bias) ----------------
// BM=128, BN=64, BK=16, 256 threads, 8x4 micro-tile via packed f32x2 FMA.
// N multiple of 64, K multiple of 16, M guarded.
__global__ __launch_bounds__(256)
void sgemm(const float* __restrict__ A, const float* __restrict__ B,
           const float* __restrict__ bias, float* __restrict__ C,
           int M, int N, int K, int act) {
    const int BM = 128, BN = 64, BK = 16;
    __shared__ float As[2][BK][BM];
    __shared__ float Bs[2][BK][BN];

    int tid = threadIdx.x;
    int row0 = blockIdx.y * BM;
    int col0 = blockIdx.x * BN;
    int tr = tid / 16, tc = tid % 16;     // 16x16 threads

    // A tile: 128 rows x 16 K = 512 float4; 2 per thread
    int a_r0 = tid / 4,       a_c0 = (tid % 4) * 4;       // float4 along K
    int a_r1 = (tid + 256)/4, a_c1 = ((tid + 256) % 4) * 4;
    // B tile: 16 K x 64 N = 256 float4; 1 per thread
    int b_k = tid / 16, b_n = (tid % 16) * 4;

    unsigned long long acc[4][4];
    #pragma unroll
    for (int i = 0; i < 4; ++i)
        #pragma unroll
        for (int jj = 0; jj < 4; ++jj) acc[i][jj] = 0ULL;

    int nk = K / BK;
    float4 ra0, ra1, rb;

    // prologue: load tile 0
    {
        int gr0 = row0 + a_r0, gr1 = row0 + a_r1;
        ra0 = (gr0 < M) ? *(const float4*)&A[(long)gr0 * K + a_c0]
                        : make_float4(0,0,0,0);
        ra1 = (gr1 < M) ? *(const float4*)&A[(long)gr1 * K + a_c1]
                        : make_float4(0,0,0,0);
        rb  = *(const float4*)&B[(long)b_k * N + col0 + b_n];
        As[0][a_c0+0][a_r0] = ra0.x; As[0][a_c0+1][a_r0] = ra0.y;
        As[0][a_c0+2][a_r0] = ra0.z; As[0][a_c0+3][a_r0] = ra0.w;
        As[0][a_c1+0][a_r1] = ra1.x; As[0][a_c1+1][a_r1] = ra1.y;
        As[0][a_c1+2][a_r1] = ra1.z; As[0][a_c1+3][a_r1] = ra1.w;
        *(float4*)&Bs[0][b_k][b_n] = rb;
    }
    __syncthreads();

    int buf = 0;
    for (int kt = 0; kt < nk; ++kt) {
        int k0n = (kt + 1) * BK;
        if (kt + 1 < nk) {
            int gr0 = row0 + a_r0, gr1 = row0 + a_r1;
            ra0 = (gr0 < M) ? *(const float4*)&A[(long)gr0 * K + k0n + a_c0]
                            : make_float4(0,0,0,0);
            ra1 = (gr1 < M) ? *(const float4*)&A[(long)gr1 * K + k0n + a_c1]
                            : make_float4(0,0,0,0);
            rb  = *(const float4*)&B[(long)(k0n + b_k) * N + col0 + b_n];
        }
        #pragma unroll
        for (int kk = 0; kk < BK; ++kk) {
            unsigned long long a2[4], b2[4];
            #pragma unroll
            for (int i = 0; i < 4; ++i)
                a2[i] = *(const unsigned long long*)&As[buf][kk][tr * 8 + 2 * i];
            #pragma unroll
            for (int jj = 0; jj < 4; ++jj) {
                unsigned int bv = __float_as_uint(Bs[buf][kk][tc * 4 + jj]);
                PACK_DUP(b2[jj], bv);
            }
            #pragma unroll
            for (int i = 0; i < 4; ++i)
                #pragma unroll
                for (int jj = 0; jj < 4; ++jj)
                    FMA_F32X2(acc[i][jj], a2[i], b2[jj]);
        }
        if (kt + 1 < nk) {
            __syncthreads();
            int nb = buf ^ 1;
            As[nb][a_c0+0][a_r0] = ra0.x; As[nb][a_c0+1][a_r0] = ra0.y;
            As[nb][a_c0+2][a_r0] = ra0.z; As[nb][a_c0+3][a_r0] = ra0.w;
            As[nb][a_c1+0][a_r1] = ra1.x; As[nb][a_c1+1][a_r1] = ra1.y;
            As[nb][a_c1+2][a_r1] = ra1.z; As[nb][a_c1+3][a_r1] = ra1.w;
            *(float4*)&Bs[nb][b_k][b_n] = rb;
            __syncthreads();
            buf = nb;
        }
    }

    // epilogue
    #pragma unroll
    for (int i = 0; i < 4; ++i) {
        int r_even = row0 + tr * 8 + 2 * i;
        #pragma unroll
        for (int jj = 0; jj < 4; ++jj) {
            unsigned int ulo, uhi;
            UNPACK2(ulo, uhi, acc[i][jj]);
            int c = col0 + tc * 4 + jj;
            float bv = bias ? bias[c] : 0.0f;
            float vlo = __uint_as_float(ulo) + bv;
            float vhi = __uint_as_float(uhi) + bv;
            if (act) {
                vlo = vlo / (1.0f + expf(-vlo));
                vhi = vhi / (1.0f + expf(-vhi));
            }
            if (r_even < M)     C[(long)r_even * N + c] = vlo;
            if (r_even + 1 < M) C[(long)(r_even + 1) * N + c] = vhi;
        }
    }
}

// ---------------- edge message pass with sorted-idx register accumulation ----------------
#define EPB 50
__global__ void edge_message(const int* __restrict__ idx_i, const int* __restrict__ idx_j) {
    int t = threadIdx.x;  // 128 threads = F_DIM
    long e0 = (long)blockIdx.x * EPB;
    long e1 = e0 + EPB; if (e1 > N_EDGES) e1 = N_EDGES;
    int cur = -1;
    float aq = 0.f, a0 = 0.f, a1 = 0.f, a2 = 0.f;

    for (long e = e0; e < e1; ++e) {
        int i = idx_i[e], j = idx_j[e];
        if (i != cur) {
            if (cur >= 0) {
                atomicAdd(&g_dq[cur * F_DIM + t], aq);
                atomicAdd(&g_dmu[(cur * 3 + 0) * F_DIM + t], a0);
                atomicAdd(&g_dmu[(cur * 3 + 1) * F_DIM + t], a1);
                atomicAdd(&g_dmu[(cur * 3 + 2) * F_DIM + t], a2);
            }
            cur = i; aq = a0 = a1 = a2 = 0.f;
        }
        const float* w = &g_Wij[e * F3];
        float w0 = __ldcs(&w[t]);
        float w1 = __ldcs(&w[F_DIM + t]);
        float w2 = __ldcs(&w[2 * F_DIM + t]);
        float xj0 = g_x[(long)j * F3 + t];
        float xj1 = g_x[(long)j * F3 + F_DIM + t];
        float xj2 = g_x[(long)j * F3 + 2 * F_DIM + t];
        float m0 = g_mu[(j * 3 + 0) * F_DIM + t];
        float m1 = g_mu[(j * 3 + 1) * F_DIM + t];
        float m2 = g_mu[(j * 3 + 2) * F_DIM + t];
        float d0 = g_dir[e * 3 + 0], d1 = g_dir[e * 3 + 1], d2 = g_dir[e * 3 + 2];

        aq += w0 * xj0;
        float dmuR  = w1 * xj1;
        float dmumu = w2 * xj2;
        a0 += dmuR * d0 + dmumu * m0;
        a1 += dmuR * d1 + dmumu * m1;
        a2 += dmuR * d2 + dmumu * m2;
    }
    if (cur >= 0) {
        atomicAdd(&g_dq[cur * F_DIM + t], aq);
        atomicAdd(&g_dmu[(cur * 3 + 0) * F_DIM + t], a0);
        atomicAdd(&g_dmu[(cur * 3 + 1) * F_DIM + t], a1);
        atomicAdd(&g_dmu[(cur * 3 + 2) * F_DIM + t], a2);
    }
}

// ---------------- apply message deltas ----------------
__global__ void apply_deltas() {
    int n = blockIdx.x, t = threadIdx.x;
    g_q[n * F_DIM + t] += g_dq[n * F_DIM + t];
    #pragma unroll
    for (int a = 0; a < 3; ++a)
        g_mu[(n * 3 + a) * F_DIM + t] += g_dmu[(n * 3 + a) * F_DIM + t];
}

// ---------------- mixing: ctx = [q, ||mu_V||] ----------------
__global__ void ctx_kernel() {
    int n = blockIdx.x, t = threadIdx.x;
    float s = EPSV;
    #pragma unroll
    for (int a = 0; a < 3; ++a) {
        float v = g_mumix[(n * 3 + a) * (2 * F_DIM) + t];
        s += v * v;
    }
    g_ctx[n * 2 * F_DIM + t] = g_q[n * F_DIM + t];
    g_ctx[n * 2 * F_DIM + F_DIM + t] = sqrtf(s);
}

// ---------------- mixing update ----------------
__global__ void mix_update() {
    int n = blockIdx.x, t = threadIdx.x;
    float dq   = g_xm[n * F3 + t];
    float dmu  = g_xm[n * F3 + F_DIM + t];
    float dqmu = g_xm[n * F3 + 2 * F_DIM + t];
    float s = 0.f;
    #pragma unroll
    for (int a = 0; a < 3; ++a) {
        float v = g_mumix[(n * 3 + a) * (2 * F_DIM) + t];
        float w = g_mumix[(n * 3 + a) * (2 * F_DIM) + F_DIM + t];
        s += v * w;
        g_mu[(n * 3 + a) * F_DIM + t] += dmu * w;
    }
    g_q[n * F_DIM + t] += dq + dqmu * s;
}

// ---------------- host launch ----------------
extern "C" void kernel_launch(void* const* d_in, const int* in_sizes, int n_in,
                              void* d_out, int out_size) {
    (void)in_sizes; (void)n_in;
    const int*   Z       = (const int*)  d_in[0];
    const float* R       = (const float*)d_in[1];
    const int*   idx_i   = (const int*)  d_in[2];
    const int*   idx_j   = (const int*)  d_in[3];
    const float* offs    = (const float*)d_in[4];
    const float* emb     = (const float*)d_in[5];
    const float* filt_W  = (const float*)d_in[6];
    const float* filt_b  = (const float*)d_in[7];
    const float* int_W1  = (const float*)d_in[8];
    const float* int_b1  = (const float*)d_in[9];
    const float* int_W2  = (const float*)d_in[10];
    const float* int_b2  = (const float*)d_in[11];
    const float* mix_Wmu = (const float*)d_in[12];
    const float* mix_W1  = (const float*)d_in[13];
    const float* mix_b1  = (const float*)d_in[14];
    const float* mix_W2  = (const float*)d_in[15];
    const float* mix_b2  = (const float*)d_in[16];
    float* out = (float*)d_out;
    (void)out_size;

    void *p_q, *p_mu, *p_h, *p_x, *p_dq, *p_dmu, *p_mumix, *p_ctx, *p_hm, *p_xm;
    cudaGetSymbolAddress(&p_q, g_q);
    cudaGetSymbolAddress(&p_mu, g_mu);
    cudaGetSymbolAddress(&p_h, g_h);
    cudaGetSymbolAddress(&p_x, g_x);
    cudaGetSymbolAddress(&p_dq, g_dq);
    cudaGetSymbolAddress(&p_dmu, g_dmu);
    cudaGetSymbolAddress(&p_mumix, g_mumix);
    cudaGetSymbolAddress(&p_ctx, g_ctx);
    cudaGetSymbolAddress(&p_hm, g_hm);
    cudaGetSymbolAddress(&p_xm, g_xm);

    // 1) edge precompute
    edge_pre<<<N_EDGES, 128>>>(R, idx_i, idx_j, offs, filt_W, filt_b);
    // 2) init
    init_atoms<<<N_ATOMS, 128>>>(Z, emb);

    dim3 blk(256);
    const int BM = 128;
    for (int it = 0; it < 3; ++it) {
        // interaction atom-wise MLP
        sgemm<<<dim3(F_DIM / 64, (N_ATOMS + BM - 1) / BM), blk>>>(
            (const float*)p_q, int_W1 + (long)it * F_DIM * F_DIM,
            int_b1 + (long)it * F_DIM, (float*)p_h, N_ATOMS, F_DIM, F_DIM, 1);
        sgemm<<<dim3(F3 / 64, (N_ATOMS + BM - 1) / BM), blk>>>(
            (const float*)p_h, int_W2 + (long)it * F_DIM * F3,
            int_b2 + (long)it * F3, (float*)p_x, N_ATOMS, F3, F_DIM, 0);

        // message pass
        cudaMemsetAsync(p_dq, 0, (size_t)N_ATOMS * F_DIM * sizeof(float));
        cudaMemsetAsync(p_dmu, 0, (size_t)N_ATOMS * 3 * F_DIM * sizeof(float));
        edge_message<<<(N_EDGES + EPB - 1) / EPB, 128>>>(idx_i, idx_j);
        apply_deltas<<<N_ATOMS, 128>>>();

        // mixing
        sgemm<<<dim3(2 * F_DIM / 64, (3 * N_ATOMS + BM - 1) / BM), blk>>>(
            (const float*)p_mu, mix_Wmu + (long)it * F_DIM * 2 * F_DIM,
            nullptr, (float*)p_mumix, 3 * N_ATOMS, 2 * F_DIM, F_DIM, 0);
        ctx_kernel<<<N_ATOMS, 128>>>();
        sgemm<<<dim3(F_DIM / 64, (N_ATOMS + BM - 1) / BM), blk>>>(
            (const float*)p_ctx, mix_W1 + (long)it * 2 * F_DIM * F_DIM,
            mix_b1 + (long)it * F_DIM, (float*)p_hm, N_ATOMS, F_DIM, 2 * F_DIM, 1);
        sgemm<<<dim3(F3 / 64, (N_ATOMS + BM - 1) / BM), blk>>>(
            (const float*)p_hm, mix_W2 + (long)it * F_DIM * F3,
            mix_b2 + (long)it * F3, (float*)p_xm, N_ATOMS, F3, F_DIM, 0);
        mix_update<<<N_ATOMS, 128>>>();
    }

    // output: q [N,F] then mu [N,3,F]
    cudaMemcpyAsync(out, p_q, (size_t)N_ATOMS * F_DIM * sizeof(float),
                    cudaMemcpyDeviceToDevice);
    cudaMemcpyAsync(out + (size_t)N_ATOMS * F_DIM, p_mu,
                    (size_t)N_ATOMS * 3 * F_DIM * sizeof(float),
                    cudaMemcpyDeviceToDevice);
}

// round 3
// speedup vs baseline: 1.6883x; 1.6883x over previous
#include <cuda_runtime.h>
#include <cuda_bf16.h>
#include <math.h>

#define N_ATOMS 10000
#define N_EDGES 250000
#define F_DIM   128
#define F3      384
#define N_RBF   20
#define CUTOFF  5.0f
#define EPSV    1e-8f
#define NTAB    8192          // W(d) lookup rows over [0, CUTOFF]

// ---------------- scratch (device globals; no allocation allowed) ----------------
__device__ float g_tab [(size_t)NTAB * F3];      // 12.6 MB W(d) table (L2-resident)
__device__ float g_d   [N_EDGES];
__device__ float g_dir [(size_t)N_EDGES * 3];
__device__ float g_q   [N_ATOMS * F_DIM];
__device__ float g_mu  [N_ATOMS * 3 * F_DIM];
__device__ float g_h   [N_ATOMS * F_DIM];
__device__ float g_x   [N_ATOMS * F3];
__device__ float g_dq  [N_ATOMS * F_DIM];
__device__ float g_dmu [N_ATOMS * 3 * F_DIM];
__device__ float g_mumix[N_ATOMS * 3 * 2 * F_DIM];
__device__ float g_ctx [N_ATOMS * 2 * F_DIM];
__device__ float g_hm  [N_ATOMS * F_DIM];
__device__ float g_xm  [N_ATOMS * F3];

// ---------------- edge geometry: d + dir ----------------
__global__ void edge_geom(const float* __restrict__ R,
                          const int* __restrict__ idx_i,
                          const int* __restrict__ idx_j,
                          const float* __restrict__ offs) {
    int e = blockIdx.x * blockDim.x + threadIdx.x;
    if (e >= N_EDGES) return;
    int i = idx_i[e], j = idx_j[e];
    float rx = R[j*3+0] - R[i*3+0] + offs[e*3+0];
    float ry = R[j*3+1] - R[i*3+1] + offs[e*3+1];
    float rz = R[j*3+2] - R[i*3+2] + offs[e*3+2];
    float d = sqrtf(rx*rx + ry*ry + rz*rz);
    float inv = 1.0f / d;
    g_d[e] = d;
    g_dir[e*3+0] = rx*inv;
    g_dir[e*3+1] = ry*inv;
    g_dir[e*3+2] = rz*inv;
}

// ---------------- build W(d) table: row k = (phi(d_k) @ filt_W + b) * fcut(d_k) ----------------
__global__ void build_table(const float* __restrict__ filt_W,
                            const float* __restrict__ filt_b) {
    int k = blockIdx.x;          // 0..NTAB-1
    int c = threadIdx.x;         // 0..383
    __shared__ float s_phi[N_RBF];
    const float step = CUTOFF / (float)(NTAB - 1);
    float d = (float)k * step;
    if (c < N_RBF) {
        const float spacing = CUTOFF / (float)(N_RBF - 1);
        const float coeff = -0.5f / (spacing * spacing);
        float dd = d - (float)c * spacing;
        s_phi[c] = expf(coeff * dd * dd);
    }
    __syncthreads();
    float fc = (d < CUTOFF) ? 0.5f * (cosf(d * (float)(M_PI / 5.0)) + 1.0f) : 0.0f;
    float acc = filt_b[c];
    #pragma unroll
    for (int r = 0; r < N_RBF; ++r)
        acc += s_phi[r] * filt_W[r * F3 + c];
    g_tab[(size_t)k * F3 + c] = acc * fc;
}

// ---------------- init: q = emb[Z], mu = 0, deltas = 0 ----------------
__global__ void init_atoms(const int* __restrict__ Z, const float* __restrict__ emb) {
    int n = blockIdx.x, t = threadIdx.x;
    int z = Z[n];
    g_q[n * F_DIM + t] = emb[z * F_DIM + t];
    g_dq[n * F_DIM + t] = 0.0f;
    #pragma unroll
    for (int a = 0; a < 3; ++a) {
        g_mu [(n * 3 + a) * F_DIM + t] = 0.0f;
        g_dmu[(n * 3 + a) * F_DIM + t] = 0.0f;
    }
}

// ---------------- simple tiled SGEMM: C = act(A[M,K] @ B[K,N] + bias) ----------------
// N multiple of 64, K multiple of 16. M guarded. (R1 version — known 20 TF/s)
__global__ void sgemm(const float* __restrict__ A, const float* __restrict__ B,
                      const float* __restrict__ bias, float* __restrict__ C,
                      int M, int N, int K, int act) {
    const int BM = 64, BN = 64, BK = 16;
    __shared__ float As[BK][BM];
    __shared__ float Bs[BK][BN];
    int tid = threadIdx.x;               // 256 threads
    int row0 = blockIdx.y * BM;
    int col0 = blockIdx.x * BN;
    int tr = tid / 16, tc = tid % 16;    // 16x16 threads, 4x4 micro-tile
    float acc[4][4] = {};

    for (int k0 = 0; k0 < K; k0 += BK) {
        #pragma unroll
        for (int l = 0; l < 4; ++l) {
            int idx = tid + l * 256;
            int m = idx / BK, kk = idx % BK;
            int gr = row0 + m;
            As[kk][m] = (gr < M) ? A[(long)gr * K + k0 + kk] : 0.0f;
        }
        #pragma unroll
        for (int l = 0; l < 4; ++l) {
            int idx = tid + l * 256;
            int kk = idx / BN, n = idx % BN;
            Bs[kk][n] = B[(long)(k0 + kk) * N + col0 + n];
        }
        __syncthreads();
        #pragma unroll
        for (int kk = 0; kk < BK; ++kk) {
            float a[4], b[4];
            #pragma unroll
            for (int i = 0; i < 4; ++i) a[i] = As[kk][tr * 4 + i];
            #pragma unroll
            for (int j = 0; j < 4; ++j) b[j] = Bs[kk][tc * 4 + j];
            #pragma unroll
            for (int i = 0; i < 4; ++i)
                #pragma unroll
                for (int j = 0; j < 4; ++j)
                    acc[i][j] += a[i] * b[j];
        }
        __syncthreads();
    }
    #pragma unroll
    for (int i = 0; i < 4; ++i) {
        int r = row0 + tr * 4 + i;
        if (r >= M) continue;
        #pragma unroll
        for (int j = 0; j < 4; ++j) {
            int c = col0 + tc * 4 + j;
            float v = acc[i][j] + (bias ? bias[c] : 0.0f);
            if (act) v = v / (1.0f + expf(-v));   // silu
            C[(long)r * N + c] = v;
        }
    }
}

// ---------------- edge message pass: table-lerp W + sorted-idx register accumulation ----------------
#define EPB 50
__global__ void edge_message(const int* __restrict__ idx_i, const int* __restrict__ idx_j) {
    int t = threadIdx.x;  // 128 threads = F_DIM
    long e0 = (long)blockIdx.x * EPB;
    long e1 = e0 + EPB; if (e1 > N_EDGES) e1 = N_EDGES;
    int cur = -1;
    float aq = 0.f, a0 = 0.f, a1 = 0.f, a2 = 0.f;
    const float inv_step = (float)(NTAB - 1) / CUTOFF;

    for (long e = e0; e < e1; ++e) {
        int i = idx_i[e];
        if (i != cur) {
            if (cur >= 0) {
                atomicAdd(&g_dq[cur * F_DIM + t], aq);
                atomicAdd(&g_dmu[(cur * 3 + 0) * F_DIM + t], a0);
                atomicAdd(&g_dmu[(cur * 3 + 1) * F_DIM + t], a1);
                atomicAdd(&g_dmu[(cur * 3 + 2) * F_DIM + t], a2);
            }
            cur = i; aq = a0 = a1 = a2 = 0.f;
        }
        float d = g_d[e];
        if (d >= CUTOFF) continue;          // fcut = 0 -> zero message (block-uniform branch)
        int j = idx_j[e];

        float u = d * inv_step;
        int k = (int)u; if (k > NTAB - 2) k = NTAB - 2;
        float f = u - (float)k;
        const float* t0 = &g_tab[(size_t)k * F3];
        const float* t1 = t0 + F3;
        float w0 = fmaf(f, t1[t]           - t0[t],           t0[t]);
        float w1 = fmaf(f, t1[F_DIM + t]   - t0[F_DIM + t],   t0[F_DIM + t]);
        float w2 = fmaf(f, t1[2*F_DIM + t] - t0[2*F_DIM + t], t0[2*F_DIM + t]);

        float xj0 = g_x[(long)j * F3 + t];
        float xj1 = g_x[(long)j * F3 + F_DIM + t];
        float xj2 = g_x[(long)j * F3 + 2 * F_DIM + t];
        float m0 = g_mu[(j * 3 + 0) * F_DIM + t];
        float m1 = g_mu[(j * 3 + 1) * F_DIM + t];
        float m2 = g_mu[(j * 3 + 2) * F_DIM + t];
        float d0 = g_dir[e * 3 + 0], d1 = g_dir[e * 3 + 1], d2 = g_dir[e * 3 + 2];

        aq += w0 * xj0;
        float dmuR  = w1 * xj1;
        float dmumu = w2 * xj2;
        a0 += dmuR * d0 + dmumu * m0;
        a1 += dmuR * d1 + dmumu * m1;
        a2 += dmuR * d2 + dmumu * m2;
    }
    if (cur >= 0) {
        atomicAdd(&g_dq[cur * F_DIM + t], aq);
        atomicAdd(&g_dmu[(cur * 3 + 0) * F_DIM + t], a0);
        atomicAdd(&g_dmu[(cur * 3 + 1) * F_DIM + t], a1);
        atomicAdd(&g_dmu[(cur * 3 + 2) * F_DIM + t], a2);
    }
}

// ---------------- apply message deltas (and re-zero delta buffers) ----------------
__global__ void apply_deltas() {
    int n = blockIdx.x, t = threadIdx.x;
    g_q[n * F_DIM + t] += g_dq[n * F_DIM + t];
    g_dq[n * F_DIM + t] = 0.0f;
    #pragma unroll
    for (int a = 0; a < 3; ++a) {
        g_mu[(n * 3 + a) * F_DIM + t] += g_dmu[(n * 3 + a) * F_DIM + t];
        g_dmu[(n * 3 + a) * F_DIM + t] = 0.0f;
    }
}

// ---------------- mixing: ctx = [q, ||mu_V||] ----------------
__global__ void ctx_kernel() {
    int n = blockIdx.x, t = threadIdx.x;
    float s = EPSV;
    #pragma unroll
    for (int a = 0; a < 3; ++a) {
        float v = g_mumix[(n * 3 + a) * (2 * F_DIM) + t];
        s += v * v;
    }
    g_ctx[n * 2 * F_DIM + t] = g_q[n * F_DIM + t];
    g_ctx[n * 2 * F_DIM + F_DIM + t] = sqrtf(s);
}

// ---------------- mixing update ----------------
__global__ void mix_update() {
    int n = blockIdx.x, t = threadIdx.x;
    float dq   = g_xm[n * F3 + t];
    float dmu  = g_xm[n * F3 + F_DIM + t];
    float dqmu = g_xm[n * F3 + 2 * F_DIM + t];
    float s = 0.f;
    #pragma unroll
    for (int a = 0; a < 3; ++a) {
        float v = g_mumix[(n * 3 + a) * (2 * F_DIM) + t];
        float w = g_mumix[(n * 3 + a) * (2 * F_DIM) + F_DIM + t];
        s += v * w;
        g_mu[(n * 3 + a) * F_DIM + t] += dmu * w;
    }
    g_q[n * F_DIM + t] += dq + dqmu * s;
}

// ---------------- host launch ----------------
extern "C" void kernel_launch(void* const* d_in, const int* in_sizes, int n_in,
                              void* d_out, int out_size) {
    (void)in_sizes; (void)n_in;
    const int*   Z       = (const int*)  d_in[0];
    const float* R       = (const float*)d_in[1];
    const int*   idx_i   = (const int*)  d_in[2];
    const int*   idx_j   = (const int*)  d_in[3];
    const float* offs    = (const float*)d_in[4];
    const float* emb     = (const float*)d_in[5];
    const float* filt_W  = (const float*)d_in[6];
    const float* filt_b  = (const float*)d_in[7];
    const float* int_W1  = (const float*)d_in[8];
    const float* int_b1  = (const float*)d_in[9];
    const float* int_W2  = (const float*)d_in[10];
    const float* int_b2  = (const float*)d_in[11];
    const float* mix_Wmu = (const float*)d_in[12];
    const float* mix_W1  = (const float*)d_in[13];
    const float* mix_b1  = (const float*)d_in[14];
    const float* mix_W2  = (const float*)d_in[15];
    const float* mix_b2  = (const float*)d_in[16];
    float* out = (float*)d_out;
    (void)out_size;

    void *p_q, *p_mu, *p_h, *p_x, *p_mumix, *p_ctx, *p_hm, *p_xm;
    cudaGetSymbolAddress(&p_q, g_q);
    cudaGetSymbolAddress(&p_mu, g_mu);
    cudaGetSymbolAddress(&p_h, g_h);
    cudaGetSymbolAddress(&p_x, g_x);
    cudaGetSymbolAddress(&p_mumix, g_mumix);
    cudaGetSymbolAddress(&p_ctx, g_ctx);
    cudaGetSymbolAddress(&p_hm, g_hm);
    cudaGetSymbolAddress(&p_xm, g_xm);

    // 1) precompute: geometry, W(d) table, init atoms (+zero deltas)
    edge_geom<<<(N_EDGES + 255) / 256, 256>>>(R, idx_i, idx_j, offs);
    build_table<<<NTAB, F3>>>(filt_W, filt_b);
    init_atoms<<<N_ATOMS, 128>>>(Z, emb);

    dim3 blk(256);
    for (int it = 0; it < 3; ++it) {
        // interaction atom-wise MLP
        sgemm<<<dim3(F_DIM / 64, (N_ATOMS + 63) / 64), blk>>>(
            (const float*)p_q, int_W1 + (long)it * F_DIM * F_DIM,
            int_b1 + (long)it * F_DIM, (float*)p_h, N_ATOMS, F_DIM, F_DIM, 1);
        sgemm<<<dim3(F3 / 64, (N_ATOMS + 63) / 64), blk>>>(
            (const float*)p_h, int_W2 + (long)it * F_DIM * F3,
            int_b2 + (long)it * F3, (float*)p_x, N_ATOMS, F3, F_DIM, 0);

        // message pass (deltas already zeroed by init/apply)
        edge_message<<<(N_EDGES + EPB - 1) / EPB, 128>>>(idx_i, idx_j);
        apply_deltas<<<N_ATOMS, 128>>>();

        // mixing
        sgemm<<<dim3(2 * F_DIM / 64, (3 * N_ATOMS + 63) / 64), blk>>>(
            (const float*)p_mu, mix_Wmu + (long)it * F_DIM * 2 * F_DIM,
            nullptr, (float*)p_mumix, 3 * N_ATOMS, 2 * F_DIM, F_DIM, 0);
        ctx_kernel<<<N_ATOMS, 128>>>();
        sgemm<<<dim3(F_DIM / 64, (N_ATOMS + 63) / 64), blk>>>(
            (const float*)p_ctx, mix_W1 + (long)it * 2 * F_DIM * F_DIM,
            mix_b1 + (long)it * F_DIM, (float*)p_hm, N_ATOMS, F_DIM, 2 * F_DIM, 1);
        sgemm<<<dim3(F3 / 64, (N_ATOMS + 63) / 64), blk>>>(
            (const float*)p_hm, mix_W2 + (long)it * F_DIM * F3,
            mix_b2 + (long)it * F3, (float*)p_xm, N_ATOMS, F3, F_DIM, 0);
        mix_update<<<N_ATOMS, 128>>>();
    }

    // output: q [N,F] then mu [N,3,F]
    cudaMemcpyAsync(out, p_q, (size_t)N_ATOMS * F_DIM * sizeof(float),
                    cudaMemcpyDeviceToDevice);
    cudaMemcpyAsync(out + (size_t)N_ATOMS * F_DIM, p_mu,
                    (size_t)N_ATOMS * 3 * F_DIM * sizeof(float),
                    cudaMemcpyDeviceToDevice);
}

// round 5
// speedup vs baseline: 2.4054x; 1.4248x over previous
#include <cuda_runtime.h>
#include <cuda_bf16.h>
#include <math.h>
#include <stdint.h>

#define N_ATOMS 10000
#define N_EDGES 250000
#define F_DIM   128
#define F3      384
#define N_RBF   20
#define CUTOFF  5.0f
#define EPSV    1e-8f
#define NTAB    8192

// ---------------- scratch (device globals; no allocation allowed) ----------------
__device__ float g_tab [(size_t)NTAB * F3];
__device__ float g_d   [N_EDGES];
__device__ float g_dir [(size_t)N_EDGES * 3];
__device__ float g_q   [N_ATOMS * F_DIM];
__device__ float g_mu  [N_ATOMS * 3 * F_DIM];
__device__ float g_h   [N_ATOMS * F_DIM];
__device__ float g_x   [N_ATOMS * F3];
__device__ float g_dq  [N_ATOMS * F_DIM];
__device__ float g_dmu [N_ATOMS * 3 * F_DIM];
__device__ float g_mumix[N_ATOMS * 3 * 2 * F_DIM];
__device__ float g_ctx [N_ATOMS * 2 * F_DIM];
__device__ float g_hm  [N_ATOMS * F_DIM];
__device__ float g_xm  [N_ATOMS * F3];
__device__ __nv_bfloat16 g_wH[2 * F_DIM * F3];   // transposed hi weights [N,K] (max 256x384... stored as N*K)
__device__ __nv_bfloat16 g_wL[2 * F_DIM * F3];   // transposed lo weights

__device__ __forceinline__ void split_bf16(float v, __nv_bfloat16& h, __nv_bfloat16& l) {
    h = __float2bfloat16(v);
    l = __float2bfloat16(v - __bfloat162float(h));
}

// D += A(16x16 bf16, row) @ B(16x8 bf16, col) ; f32 accum
#define MMA16816(d, a, b) \
    asm volatile("mma.sync.aligned.m16n8k16.row.col.f32.bf16.bf16.f32 " \
        "{%0,%1,%2,%3}, {%4,%5,%6,%7}, {%8,%9}, {%0,%1,%2,%3};" \
        : "+f"((d)[0]), "+f"((d)[1]), "+f"((d)[2]), "+f"((d)[3]) \
        : "r"((a)[0]), "r"((a)[1]), "r"((a)[2]), "r"((a)[3]), \
          "r"((b)[0]), "r"((b)[1]))

// ---------------- weight transpose + bf16 hi/lo split: Wt[n][k] = W[k][n] ----------------
__global__ void transpose_split(const float* __restrict__ W,
                                __nv_bfloat16* __restrict__ WtH,
                                __nv_bfloat16* __restrict__ WtL, int K, int N) {
    int idx = blockIdx.x * blockDim.x + threadIdx.x;
    if (idx >= K * N) return;
    int k = idx / N, n = idx % N;
    __nv_bfloat16 h, l;
    split_bf16(W[idx], h, l);
    WtH[(size_t)n * K + k] = h;
    WtL[(size_t)n * K + k] = l;
}

// ================= tensor-core GEMM via mma.sync (bf16x3 split) =================
// C[M,N] = act(A[M,K] @ W[K,N] + bias); weights given transposed+split [N,K].
// Block tile 128x64, 8 warps (4m x 2n), warp tile 32x32; BK=32. N%64==0, K%32==0.
__global__ __launch_bounds__(256)
void mma_gemm(const float* __restrict__ A,
              const __nv_bfloat16* __restrict__ BH,
              const __nv_bfloat16* __restrict__ BL,
              const float* __restrict__ bias, float* __restrict__ C,
              int M, int N, int K, int act) {
    __shared__ __nv_bfloat16 AsH[128][40], AsL[128][40];   // +8 pad: conflict-free frags
    __shared__ __nv_bfloat16 BsH[64][40],  BsL[64][40];

    int tid = threadIdx.x, wid = tid >> 5, lane = tid & 31;
    int row0 = blockIdx.y * 128, col0 = blockIdx.x * 64;
    int wm = wid >> 1, wn = wid & 1;          // 4x2 warp grid
    int gID = lane >> 2, tig = lane & 3;

    float acc[2][4][4];
    #pragma unroll
    for (int mt = 0; mt < 2; ++mt)
        #pragma unroll
        for (int nt = 0; nt < 4; ++nt)
            #pragma unroll
            for (int i = 0; i < 4; ++i) acc[mt][nt][i] = 0.f;

    for (int k0 = 0; k0 < K; k0 += 32) {
        // stage A: 128x32 fp32 -> bf16 hi/lo
        #pragma unroll
        for (int p = 0; p < 4; ++p) {
            int r = (tid >> 3) + p * 32;
            int c = (tid & 7) * 4;
            int gr = row0 + r;
            float4 v = (gr < M) ? *(const float4*)&A[(size_t)gr * K + k0 + c]
                                : make_float4(0.f, 0.f, 0.f, 0.f);
            __nv_bfloat16 h, l;
            split_bf16(v.x, h, l); AsH[r][c+0] = h; AsL[r][c+0] = l;
            split_bf16(v.y, h, l); AsH[r][c+1] = h; AsL[r][c+1] = l;
            split_bf16(v.z, h, l); AsH[r][c+2] = h; AsL[r][c+2] = l;
            split_bf16(v.w, h, l); AsH[r][c+3] = h; AsL[r][c+3] = l;
        }
        // stage B: 64x32 bf16 hi/lo (already [N,K])
        {
            int r = tid >> 2;
            int c = (tid & 3) * 8;
            *(uint4*)&BsH[r][c] = *(const uint4*)&BH[(size_t)(col0 + r) * K + k0 + c];
            *(uint4*)&BsL[r][c] = *(const uint4*)&BL[(size_t)(col0 + r) * K + k0 + c];
        }
        __syncthreads();

        #pragma unroll
        for (int ks = 0; ks < 32; ks += 16) {
            uint32_t ah[2][4], al[2][4], bh[4][2], bl[4][2];
            int cc = ks + tig * 2;
            #pragma unroll
            for (int mt = 0; mt < 2; ++mt) {
                int r = wm * 32 + mt * 16 + gID;
                ah[mt][0] = *(const uint32_t*)&AsH[r][cc];
                ah[mt][1] = *(const uint32_t*)&AsH[r + 8][cc];
                ah[mt][2] = *(const uint32_t*)&AsH[r][cc + 8];
                ah[mt][3] = *(const uint32_t*)&AsH[r + 8][cc + 8];
                al[mt][0] = *(const uint32_t*)&AsL[r][cc];
                al[mt][1] = *(const uint32_t*)&AsL[r + 8][cc];
                al[mt][2] = *(const uint32_t*)&AsL[r][cc + 8];
                al[mt][3] = *(const uint32_t*)&AsL[r + 8][cc + 8];
            }
            #pragma unroll
            for (int nt = 0; nt < 4; ++nt) {
                int cr = wn * 32 + nt * 8 + gID;
                bh[nt][0] = *(const uint32_t*)&BsH[cr][cc];
                bh[nt][1] = *(const uint32_t*)&BsH[cr][cc + 8];
                bl[nt][0] = *(const uint32_t*)&BsL[cr][cc];
                bl[nt][1] = *(const uint32_t*)&BsL[cr][cc + 8];
            }
            #pragma unroll
            for (int mt = 0; mt < 2; ++mt)
                #pragma unroll
                for (int nt = 0; nt < 4; ++nt) {
                    MMA16816(acc[mt][nt], ah[mt], bh[nt]);
                    MMA16816(acc[mt][nt], ah[mt], bl[nt]);
                    MMA16816(acc[mt][nt], al[mt], bh[nt]);
                }
        }
        __syncthreads();
    }

    // epilogue: bias + optional silu
    #pragma unroll
    for (int mt = 0; mt < 2; ++mt) {
        int r = row0 + wm * 32 + mt * 16 + gID;
        #pragma unroll
        for (int nt = 0; nt < 4; ++nt) {
            int c = col0 + wn * 32 + nt * 8 + tig * 2;
            float b0 = bias ? bias[c] : 0.f;
            float b1 = bias ? bias[c + 1] : 0.f;
            float v00 = acc[mt][nt][0] + b0, v01 = acc[mt][nt][1] + b1;
            float v10 = acc[mt][nt][2] + b0, v11 = acc[mt][nt][3] + b1;
            if (act) {
                v00 = v00 / (1.0f + expf(-v00));
                v01 = v01 / (1.0f + expf(-v01));
                v10 = v10 / (1.0f + expf(-v10));
                v11 = v11 / (1.0f + expf(-v11));
            }
            if (r < M)     { C[(size_t)r * N + c] = v00;       C[(size_t)r * N + c + 1] = v01; }
            if (r + 8 < M) { C[(size_t)(r + 8) * N + c] = v10; C[(size_t)(r + 8) * N + c + 1] = v11; }
        }
    }
}

// ================= PaiNN pipeline kernels (unchanged from R3) =================
__global__ void edge_geom(const float* __restrict__ R,
                          const int* __restrict__ idx_i,
                          const int* __restrict__ idx_j,
                          const float* __restrict__ offs) {
    int e = blockIdx.x * blockDim.x + threadIdx.x;
    if (e >= N_EDGES) return;
    int i = idx_i[e], j = idx_j[e];
    float rx = R[j*3+0] - R[i*3+0] + offs[e*3+0];
    float ry = R[j*3+1] - R[i*3+1] + offs[e*3+1];
    float rz = R[j*3+2] - R[i*3+2] + offs[e*3+2];
    float d = sqrtf(rx*rx + ry*ry + rz*rz);
    float inv = 1.0f / d;
    g_d[e] = d;
    g_dir[e*3+0] = rx*inv;
    g_dir[e*3+1] = ry*inv;
    g_dir[e*3+2] = rz*inv;
}

__global__ void build_table(const float* __restrict__ filt_W,
                            const float* __restrict__ filt_b) {
    int k = blockIdx.x;
    int c = threadIdx.x;
    __shared__ float s_phi[N_RBF];
    const float step = CUTOFF / (float)(NTAB - 1);
    float d = (float)k * step;
    if (c < N_RBF) {
        const float spacing = CUTOFF / (float)(N_RBF - 1);
        const float coeff = -0.5f / (spacing * spacing);
        float dd = d - (float)c * spacing;
        s_phi[c] = expf(coeff * dd * dd);
    }
    __syncthreads();
    float fc = (d < CUTOFF) ? 0.5f * (cosf(d * (float)(M_PI / 5.0)) + 1.0f) : 0.0f;
    float acc = filt_b[c];
    #pragma unroll
    for (int r = 0; r < N_RBF; ++r)
        acc += s_phi[r] * filt_W[r * F3 + c];
    g_tab[(size_t)k * F3 + c] = acc * fc;
}

__global__ void init_atoms(const int* __restrict__ Z, const float* __restrict__ emb) {
    int n = blockIdx.x, t = threadIdx.x;
    int z = Z[n];
    g_q[n * F_DIM + t] = emb[z * F_DIM + t];
    g_dq[n * F_DIM + t] = 0.0f;
    #pragma unroll
    for (int a = 0; a < 3; ++a) {
        g_mu [(n * 3 + a) * F_DIM + t] = 0.0f;
        g_dmu[(n * 3 + a) * F_DIM + t] = 0.0f;
    }
}

#define EPB 50
__global__ void edge_message(const int* __restrict__ idx_i, const int* __restrict__ idx_j) {
    int t = threadIdx.x;
    long e0 = (long)blockIdx.x * EPB;
    long e1 = e0 + EPB; if (e1 > N_EDGES) e1 = N_EDGES;
    int cur = -1;
    float aq = 0.f, a0 = 0.f, a1 = 0.f, a2 = 0.f;
    const float inv_step = (float)(NTAB - 1) / CUTOFF;

    for (long e = e0; e < e1; ++e) {
        int i = idx_i[e];
        if (i != cur) {
            if (cur >= 0) {
                atomicAdd(&g_dq[cur * F_DIM + t], aq);
                atomicAdd(&g_dmu[(cur * 3 + 0) * F_DIM + t], a0);
                atomicAdd(&g_dmu[(cur * 3 + 1) * F_DIM + t], a1);
                atomicAdd(&g_dmu[(cur * 3 + 2) * F_DIM + t], a2);
            }
            cur = i; aq = a0 = a1 = a2 = 0.f;
        }
        float d = g_d[e];
        if (d >= CUTOFF) continue;
        int j = idx_j[e];

        float u = d * inv_step;
        int k = (int)u; if (k > NTAB - 2) k = NTAB - 2;
        float f = u - (float)k;
        const float* t0 = &g_tab[(size_t)k * F3];
        const float* t1 = t0 + F3;
        float w0 = fmaf(f, t1[t]           - t0[t],           t0[t]);
        float w1 = fmaf(f, t1[F_DIM + t]   - t0[F_DIM + t],   t0[F_DIM + t]);
        float w2 = fmaf(f, t1[2*F_DIM + t] - t0[2*F_DIM + t], t0[2*F_DIM + t]);

        float xj0 = g_x[(long)j * F3 + t];
        float xj1 = g_x[(long)j * F3 + F_DIM + t];
        float xj2 = g_x[(long)j * F3 + 2 * F_DIM + t];
        float m0 = g_mu[(j * 3 + 0) * F_DIM + t];
        float m1 = g_mu[(j * 3 + 1) * F_DIM + t];
        float m2 = g_mu[(j * 3 + 2) * F_DIM + t];
        float d0 = g_dir[e * 3 + 0], d1 = g_dir[e * 3 + 1], d2 = g_dir[e * 3 + 2];

        aq += w0 * xj0;
        float dmuR  = w1 * xj1;
        float dmumu = w2 * xj2;
        a0 += dmuR * d0 + dmumu * m0;
        a1 += dmuR * d1 + dmumu * m1;
        a2 += dmuR * d2 + dmumu * m2;
    }
    if (cur >= 0) {
        atomicAdd(&g_dq[cur * F_DIM + t], aq);
        atomicAdd(&g_dmu[(cur * 3 + 0) * F_DIM + t], a0);
        atomicAdd(&g_dmu[(cur * 3 + 1) * F_DIM + t], a1);
        atomicAdd(&g_dmu[(cur * 3 + 2) * F_DIM + t], a2);
    }
}

__global__ void apply_deltas() {
    int n = blockIdx.x, t = threadIdx.x;
    g_q[n * F_DIM + t] += g_dq[n * F_DIM + t];
    g_dq[n * F_DIM + t] = 0.0f;
    #pragma unroll
    for (int a = 0; a < 3; ++a) {
        g_mu[(n * 3 + a) * F_DIM + t] += g_dmu[(n * 3 + a) * F_DIM + t];
        g_dmu[(n * 3 + a) * F_DIM + t] = 0.0f;
    }
}

__global__ void ctx_kernel() {
    int n = blockIdx.x, t = threadIdx.x;
    float s = EPSV;
    #pragma unroll
    for (int a = 0; a < 3; ++a) {
        float v = g_mumix[(n * 3 + a) * (2 * F_DIM) + t];
        s += v * v;
    }
    g_ctx[n * 2 * F_DIM + t] = g_q[n * F_DIM + t];
    g_ctx[n * 2 * F_DIM + F_DIM + t] = sqrtf(s);
}

__global__ void mix_update() {
    int n = blockIdx.x, t = threadIdx.x;
    float dq   = g_xm[n * F3 + t];
    float dmu  = g_xm[n * F3 + F_DIM + t];
    float dqmu = g_xm[n * F3 + 2 * F_DIM + t];
    float s = 0.f;
    #pragma unroll
    for (int a = 0; a < 3; ++a) {
        float v = g_mumix[(n * 3 + a) * (2 * F_DIM) + t];
        float w = g_mumix[(n * 3 + a) * (2 * F_DIM) + F_DIM + t];
        s += v * w;
        g_mu[(n * 3 + a) * F_DIM + t] += dmu * w;
    }
    g_q[n * F_DIM + t] += dq + dqmu * s;
}

// ================= host launch =================
extern "C" void kernel_launch(void* const* d_in, const int* in_sizes, int n_in,
                              void* d_out, int out_size) {
    (void)in_sizes; (void)n_in; (void)out_size;
    const int*   Z       = (const int*)  d_in[0];
    const float* R       = (const float*)d_in[1];
    const int*   idx_i   = (const int*)  d_in[2];
    const int*   idx_j   = (const int*)  d_in[3];
    const float* offs    = (const float*)d_in[4];
    const float* emb     = (const float*)d_in[5];
    const float* filt_W  = (const float*)d_in[6];
    const float* filt_b  = (const float*)d_in[7];
    const float* int_W1  = (const float*)d_in[8];
    const float* int_b1  = (const float*)d_in[9];
    const float* int_W2  = (const float*)d_in[10];
    const float* int_b2  = (const float*)d_in[11];
    const float* mix_Wmu = (const float*)d_in[12];
    const float* mix_W1  = (const float*)d_in[13];
    const float* mix_b1  = (const float*)d_in[14];
    const float* mix_W2  = (const float*)d_in[15];
    const float* mix_b2  = (const float*)d_in[16];
    float* out = (float*)d_out;

    void *p_q, *p_mu, *p_h, *p_x, *p_mumix, *p_ctx, *p_hm, *p_xm, *p_wH, *p_wL;
    cudaGetSymbolAddress(&p_q, g_q);
    cudaGetSymbolAddress(&p_mu, g_mu);
    cudaGetSymbolAddress(&p_h, g_h);
    cudaGetSymbolAddress(&p_x, g_x);
    cudaGetSymbolAddress(&p_mumix, g_mumix);
    cudaGetSymbolAddress(&p_ctx, g_ctx);
    cudaGetSymbolAddress(&p_hm, g_hm);
    cudaGetSymbolAddress(&p_xm, g_xm);
    cudaGetSymbolAddress(&p_wH, g_wH);
    cudaGetSymbolAddress(&p_wL, g_wL);

    // precompute
    edge_geom<<<(N_EDGES + 255) / 256, 256>>>(R, idx_i, idx_j, offs);
    build_table<<<NTAB, F3>>>(filt_W, filt_b);
    init_atoms<<<N_ATOMS, 128>>>(Z, emb);

    // tensor-core GEMM launcher: C = act(A @ W + bias)
    auto gemm = [&](const float* A, const float* W, const float* bias, float* C,
                    int M, int N, int K, int act) {
        transpose_split<<<(K * N + 255) / 256, 256>>>(
            W, (__nv_bfloat16*)p_wH, (__nv_bfloat16*)p_wL, K, N);
        mma_gemm<<<dim3(N / 64, (M + 127) / 128), 256>>>(
            A, (const __nv_bfloat16*)p_wH, (const __nv_bfloat16*)p_wL, bias, C, M, N, K, act);
    };

    for (int it = 0; it < 3; ++it) {
        // interaction atom-wise MLP
        gemm((const float*)p_q, int_W1 + (long)it * F_DIM * F_DIM,
             int_b1 + (long)it * F_DIM, (float*)p_h, N_ATOMS, F_DIM, F_DIM, 1);
        gemm((const float*)p_h, int_W2 + (long)it * F_DIM * F3,
             int_b2 + (long)it * F3, (float*)p_x, N_ATOMS, F3, F_DIM, 0);

        // message pass
        edge_message<<<(N_EDGES + EPB - 1) / EPB, 128>>>(idx_i, idx_j);
        apply_deltas<<<N_ATOMS, 128>>>();

        // mixing
        gemm((const float*)p_mu, mix_Wmu + (long)it * F_DIM * 2 * F_DIM,
             nullptr, (float*)p_mumix, 3 * N_ATOMS, 2 * F_DIM, F_DIM, 0);
        ctx_kernel<<<N_ATOMS, 128>>>();
        gemm((const float*)p_ctx, mix_W1 + (long)it * 2 * F_DIM * F_DIM,
             mix_b1 + (long)it * F_DIM, (float*)p_hm, N_ATOMS, F_DIM, 2 * F_DIM, 1);
        gemm((const float*)p_hm, mix_W2 + (long)it * F_DIM * F3,
             mix_b2 + (long)it * F3, (float*)p_xm, N_ATOMS, F3, F_DIM, 0);
        mix_update<<<N_ATOMS, 128>>>();
    }

    cudaMemcpyAsync(out, p_q, (size_t)N_ATOMS * F_DIM * sizeof(float),
                    cudaMemcpyDeviceToDevice);
    cudaMemcpyAsync(out + (size_t)N_ATOMS * F_DIM, p_mu,
                    (size_t)N_ATOMS * 3 * F_DIM * sizeof(float),
                    cudaMemcpyDeviceToDevice);
}

// round 6
// speedup vs baseline: 2.4774x; 1.0299x over previous
#include <cuda_runtime.h>
#include <cuda_bf16.h>
#include <cuda_fp16.h>
#include <math.h>
#include <stdint.h>

#define N_ATOMS 10000
#define N_EDGES 250000
#define F_DIM   128
#define F3      384
#define N_RBF   20
#define CUTOFF  5.0f
#define EPSV    1e-8f
#define NTAB    8192
#define WT_PER_ITER 180224   // 16384+49152+32768+32768+49152

// ---------------- scratch (device globals; no allocation allowed) ----------------
__device__ __half g_tab [(size_t)NTAB * F3];     // fp16 W(d) table (6.3 MB, L2-resident)
__device__ float g_d   [N_EDGES];
__device__ float g_dir [(size_t)N_EDGES * 3];
__device__ float g_q   [N_ATOMS * F_DIM];
__device__ float g_mu  [N_ATOMS * 3 * F_DIM];
__device__ float g_h   [N_ATOMS * F_DIM];
__device__ float g_x   [N_ATOMS * F3];
__device__ float g_dq  [N_ATOMS * F_DIM];
__device__ float g_dmu [N_ATOMS * 3 * F_DIM];
__device__ float g_mumix[N_ATOMS * 3 * 2 * F_DIM];
__device__ float g_ctx [N_ATOMS * 2 * F_DIM];
__device__ float g_hm  [N_ATOMS * F_DIM];
__device__ float g_xm  [N_ATOMS * F3];
__device__ __nv_bfloat16 g_wH[3 * WT_PER_ITER];  // all transposed hi weights
__device__ __nv_bfloat16 g_wL[3 * WT_PER_ITER];  // all transposed lo weights

__device__ __forceinline__ void split_bf16(float v, __nv_bfloat16& h, __nv_bfloat16& l) {
    h = __float2bfloat16(v);
    l = __float2bfloat16(v - __bfloat162float(h));
}

// D += A(16x16 bf16, row) @ B(16x8 bf16, col) ; f32 accum
#define MMA16816(d, a, b) \
    asm volatile("mma.sync.aligned.m16n8k16.row.col.f32.bf16.bf16.f32 " \
        "{%0,%1,%2,%3}, {%4,%5,%6,%7}, {%8,%9}, {%0,%1,%2,%3};" \
        : "+f"((d)[0]), "+f"((d)[1]), "+f"((d)[2]), "+f"((d)[3]) \
        : "r"((a)[0]), "r"((a)[1]), "r"((a)[2]), "r"((a)[3]), \
          "r"((b)[0]), "r"((b)[1]))

// ---------------- fused weight transpose + split for ALL 15 matrices ----------------
__global__ void transpose_all(const float* __restrict__ W1, const float* __restrict__ W2,
                              const float* __restrict__ Wmu, const float* __restrict__ M1,
                              const float* __restrict__ M2) {
    const int Ks[5]  = {128, 128, 128, 256, 128};
    const int Ns[5]  = {128, 384, 256, 128, 384};
    const int off[5] = {0, 16384, 65536, 98304, 131072};
    int m = blockIdx.y;
    int it = m / 5, s = m % 5;
    int K = Ks[s], N = Ns[s];
    int idx = blockIdx.x * blockDim.x + threadIdx.x;
    if (idx >= K * N) return;
    const float* src;
    switch (s) {
        case 0: src = W1  + (size_t)it * 16384; break;
        case 1: src = W2  + (size_t)it * 49152; break;
        case 2: src = Wmu + (size_t)it * 32768; break;
        case 3: src = M1  + (size_t)it * 32768; break;
        default: src = M2 + (size_t)it * 49152; break;
    }
    int k = idx / N, n = idx % N;
    size_t dst = (size_t)it * WT_PER_ITER + off[s] + (size_t)n * K + k;
    __nv_bfloat16 h, l;
    split_bf16(src[idx], h, l);
    g_wH[dst] = h;
    g_wL[dst] = l;
}

// ================= tensor-core GEMM via mma.sync (bf16x3 split) =================
// Block tile 128x64, 8 warps (4m x 2n), warp tile 32x32; BK=32. N%64==0, K%32==0.
__global__ __launch_bounds__(256)
void mma_gemm(const float* __restrict__ A,
              const __nv_bfloat16* __restrict__ BH,
              const __nv_bfloat16* __restrict__ BL,
              const float* __restrict__ bias, float* __restrict__ C,
              int M, int N, int K, int act) {
    __shared__ __nv_bfloat16 AsH[128][40], AsL[128][40];
    __shared__ __nv_bfloat16 BsH[64][40],  BsL[64][40];

    int tid = threadIdx.x, wid = tid >> 5, lane = tid & 31;
    int row0 = blockIdx.y * 128, col0 = blockIdx.x * 64;
    int wm = wid >> 1, wn = wid & 1;
    int gID = lane >> 2, tig = lane & 3;

    float acc[2][4][4];
    #pragma unroll
    for (int mt = 0; mt < 2; ++mt)
        #pragma unroll
        for (int nt = 0; nt < 4; ++nt)
            #pragma unroll
            for (int i = 0; i < 4; ++i) acc[mt][nt][i] = 0.f;

    for (int k0 = 0; k0 < K; k0 += 32) {
        #pragma unroll
        for (int p = 0; p < 4; ++p) {
            int r = (tid >> 3) + p * 32;
            int c = (tid & 7) * 4;
            int gr = row0 + r;
            float4 v = (gr < M) ? *(const float4*)&A[(size_t)gr * K + k0 + c]
                                : make_float4(0.f, 0.f, 0.f, 0.f);
            __nv_bfloat16 h, l;
            split_bf16(v.x, h, l); AsH[r][c+0] = h; AsL[r][c+0] = l;
            split_bf16(v.y, h, l); AsH[r][c+1] = h; AsL[r][c+1] = l;
            split_bf16(v.z, h, l); AsH[r][c+2] = h; AsL[r][c+2] = l;
            split_bf16(v.w, h, l); AsH[r][c+3] = h; AsL[r][c+3] = l;
        }
        {
            int r = tid >> 2;
            int c = (tid & 3) * 8;
            *(uint4*)&BsH[r][c] = *(const uint4*)&BH[(size_t)(col0 + r) * K + k0 + c];
            *(uint4*)&BsL[r][c] = *(const uint4*)&BL[(size_t)(col0 + r) * K + k0 + c];
        }
        __syncthreads();

        #pragma unroll
        for (int ks = 0; ks < 32; ks += 16) {
            uint32_t ah[2][4], al[2][4], bh[4][2], bl[4][2];
            int cc = ks + tig * 2;
            #pragma unroll
            for (int mt = 0; mt < 2; ++mt) {
                int r = wm * 32 + mt * 16 + gID;
                ah[mt][0] = *(const uint32_t*)&AsH[r][cc];
                ah[mt][1] = *(const uint32_t*)&AsH[r + 8][cc];
                ah[mt][2] = *(const uint32_t*)&AsH[r][cc + 8];
                ah[mt][3] = *(const uint32_t*)&AsH[r + 8][cc + 8];
                al[mt][0] = *(const uint32_t*)&AsL[r][cc];
                al[mt][1] = *(const uint32_t*)&AsL[r + 8][cc];
                al[mt][2] = *(const uint32_t*)&AsL[r][cc + 8];
                al[mt][3] = *(const uint32_t*)&AsL[r + 8][cc + 8];
            }
            #pragma unroll
            for (int nt = 0; nt < 4; ++nt) {
                int cr = wn * 32 + nt * 8 + gID;
                bh[nt][0] = *(const uint32_t*)&BsH[cr][cc];
                bh[nt][1] = *(const uint32_t*)&BsH[cr][cc + 8];
                bl[nt][0] = *(const uint32_t*)&BsL[cr][cc];
                bl[nt][1] = *(const uint32_t*)&BsL[cr][cc + 8];
            }
            #pragma unroll
            for (int mt = 0; mt < 2; ++mt)
                #pragma unroll
                for (int nt = 0; nt < 4; ++nt) {
                    MMA16816(acc[mt][nt], ah[mt], bh[nt]);
                    MMA16816(acc[mt][nt], ah[mt], bl[nt]);
                    MMA16816(acc[mt][nt], al[mt], bh[nt]);
                }
        }
        __syncthreads();
    }

    #pragma unroll
    for (int mt = 0; mt < 2; ++mt) {
        int r = row0 + wm * 32 + mt * 16 + gID;
        #pragma unroll
        for (int nt = 0; nt < 4; ++nt) {
            int c = col0 + wn * 32 + nt * 8 + tig * 2;
            float b0 = bias ? bias[c] : 0.f;
            float b1 = bias ? bias[c + 1] : 0.f;
            float v00 = acc[mt][nt][0] + b0, v01 = acc[mt][nt][1] + b1;
            float v10 = acc[mt][nt][2] + b0, v11 = acc[mt][nt][3] + b1;
            if (act) {
                v00 = v00 / (1.0f + expf(-v00));
                v01 = v01 / (1.0f + expf(-v01));
                v10 = v10 / (1.0f + expf(-v10));
                v11 = v11 / (1.0f + expf(-v11));
            }
            if (r < M)     { C[(size_t)r * N + c] = v00;       C[(size_t)r * N + c + 1] = v01; }
            if (r + 8 < M) { C[(size_t)(r + 8) * N + c] = v10; C[(size_t)(r + 8) * N + c + 1] = v11; }
        }
    }
}

// ================= PaiNN pipeline kernels =================
__global__ void edge_geom(const float* __restrict__ R,
                          const int* __restrict__ idx_i,
                          const int* __restrict__ idx_j,
                          const float* __restrict__ offs) {
    int e = blockIdx.x * blockDim.x + threadIdx.x;
    if (e >= N_EDGES) return;
    int i = idx_i[e], j = idx_j[e];
    float rx = R[j*3+0] - R[i*3+0] + offs[e*3+0];
    float ry = R[j*3+1] - R[i*3+1] + offs[e*3+1];
    float rz = R[j*3+2] - R[i*3+2] + offs[e*3+2];
    float d = sqrtf(rx*rx + ry*ry + rz*rz);
    float inv = 1.0f / d;
    g_d[e] = d;
    g_dir[e*3+0] = rx*inv;
    g_dir[e*3+1] = ry*inv;
    g_dir[e*3+2] = rz*inv;
}

__global__ void build_table(const float* __restrict__ filt_W,
                            const float* __restrict__ filt_b) {
    int k = blockIdx.x;
    int c = threadIdx.x;
    __shared__ float s_phi[N_RBF];
    const float step = CUTOFF / (float)(NTAB - 1);
    float d = (float)k * step;
    if (c < N_RBF) {
        const float spacing = CUTOFF / (float)(N_RBF - 1);
        const float coeff = -0.5f / (spacing * spacing);
        float dd = d - (float)c * spacing;
        s_phi[c] = expf(coeff * dd * dd);
    }
    __syncthreads();
    float fc = (d < CUTOFF) ? 0.5f * (cosf(d * (float)(M_PI / 5.0)) + 1.0f) : 0.0f;
    float acc = filt_b[c];
    #pragma unroll
    for (int r = 0; r < N_RBF; ++r)
        acc += s_phi[r] * filt_W[r * F3 + c];
    g_tab[(size_t)k * F3 + c] = __float2half(acc * fc);
}

__global__ void init_atoms(const int* __restrict__ Z, const float* __restrict__ emb) {
    int n = blockIdx.x, t = threadIdx.x;
    int z = Z[n];
    g_q[n * F_DIM + t] = emb[z * F_DIM + t];
    g_dq[n * F_DIM + t] = 0.0f;
    #pragma unroll
    for (int a = 0; a < 3; ++a) {
        g_mu [(n * 3 + a) * F_DIM + t] = 0.0f;
        g_dmu[(n * 3 + a) * F_DIM + t] = 0.0f;
    }
}

#define EPB 50
__global__ void edge_message(const int* __restrict__ idx_i, const int* __restrict__ idx_j) {
    int t = threadIdx.x;
    long e0 = (long)blockIdx.x * EPB;
    long e1 = e0 + EPB; if (e1 > N_EDGES) e1 = N_EDGES;
    int cur = -1;
    float aq = 0.f, a0 = 0.f, a1 = 0.f, a2 = 0.f;
    const float inv_step = (float)(NTAB - 1) / CUTOFF;

    for (long e = e0; e < e1; ++e) {
        int i = idx_i[e];
        if (i != cur) {
            if (cur >= 0) {
                atomicAdd(&g_dq[cur * F_DIM + t], aq);
                atomicAdd(&g_dmu[(cur * 3 + 0) * F_DIM + t], a0);
                atomicAdd(&g_dmu[(cur * 3 + 1) * F_DIM + t], a1);
                atomicAdd(&g_dmu[(cur * 3 + 2) * F_DIM + t], a2);
            }
            cur = i; aq = a0 = a1 = a2 = 0.f;
        }
        float d = g_d[e];
        if (d >= CUTOFF) continue;
        int j = idx_j[e];

        float u = d * inv_step;
        int k = (int)u; if (k > NTAB - 2) k = NTAB - 2;
        float f = u - (float)k;
        const __half* t0 = &g_tab[(size_t)k * F3];
        const __half* t1 = t0 + F3;
        float p00 = __half2float(t0[t]),           p01 = __half2float(t1[t]);
        float p10 = __half2float(t0[F_DIM + t]),   p11 = __half2float(t1[F_DIM + t]);
        float p20 = __half2float(t0[2*F_DIM + t]), p21 = __half2float(t1[2*F_DIM + t]);
        float w0 = fmaf(f, p01 - p00, p00);
        float w1 = fmaf(f, p11 - p10, p10);
        float w2 = fmaf(f, p21 - p20, p20);

        float xj0 = g_x[(long)j * F3 + t];
        float xj1 = g_x[(long)j * F3 + F_DIM + t];
        float xj2 = g_x[(long)j * F3 + 2 * F_DIM + t];
        float m0 = g_mu[(j * 3 + 0) * F_DIM + t];
        float m1 = g_mu[(j * 3 + 1) * F_DIM + t];
        float m2 = g_mu[(j * 3 + 2) * F_DIM + t];
        float d0 = g_dir[e * 3 + 0], d1 = g_dir[e * 3 + 1], d2 = g_dir[e * 3 + 2];

        aq += w0 * xj0;
        float dmuR  = w1 * xj1;
        float dmumu = w2 * xj2;
        a0 += dmuR * d0 + dmumu * m0;
        a1 += dmuR * d1 + dmumu * m1;
        a2 += dmuR * d2 + dmumu * m2;
    }
    if (cur >= 0) {
        atomicAdd(&g_dq[cur * F_DIM + t], aq);
        atomicAdd(&g_dmu[(cur * 3 + 0) * F_DIM + t], a0);
        atomicAdd(&g_dmu[(cur * 3 + 1) * F_DIM + t], a1);
        atomicAdd(&g_dmu[(cur * 3 + 2) * F_DIM + t], a2);
    }
}

__global__ void apply_deltas() {
    int n = blockIdx.x, t = threadIdx.x;
    g_q[n * F_DIM + t] += g_dq[n * F_DIM + t];
    g_dq[n * F_DIM + t] = 0.0f;
    #pragma unroll
    for (int a = 0; a < 3; ++a) {
        g_mu[(n * 3 + a) * F_DIM + t] += g_dmu[(n * 3 + a) * F_DIM + t];
        g_dmu[(n * 3 + a) * F_DIM + t] = 0.0f;
    }
}

__global__ void ctx_kernel() {
    int n = blockIdx.x, t = threadIdx.x;
    float s = EPSV;
    #pragma unroll
    for (int a = 0; a < 3; ++a) {
        float v = g_mumix[(n * 3 + a) * (2 * F_DIM) + t];
        s += v * v;
    }
    g_ctx[n * 2 * F_DIM + t] = g_q[n * F_DIM + t];
    g_ctx[n * 2 * F_DIM + F_DIM + t] = sqrtf(s);
}

__global__ void mix_update() {
    int n = blockIdx.x, t = threadIdx.x;
    float dq   = g_xm[n * F3 + t];
    float dmu  = g_xm[n * F3 + F_DIM + t];
    float dqmu = g_xm[n * F3 + 2 * F_DIM + t];
    float s = 0.f;
    #pragma unroll
    for (int a = 0; a < 3; ++a) {
        float v = g_mumix[(n * 3 + a) * (2 * F_DIM) + t];
        float w = g_mumix[(n * 3 + a) * (2 * F_DIM) + F_DIM + t];
        s += v * w;
        g_mu[(n * 3 + a) * F_DIM + t] += dmu * w;
    }
    g_q[n * F_DIM + t] += dq + dqmu * s;
}

// ================= host launch =================
extern "C" void kernel_launch(void* const* d_in, const int* in_sizes, int n_in,
                              void* d_out, int out_size) {
    (void)in_sizes; (void)n_in; (void)out_size;
    const int*   Z       = (const int*)  d_in[0];
    const float* R       = (const float*)d_in[1];
    const int*   idx_i   = (const int*)  d_in[2];
    const int*   idx_j   = (const int*)  d_in[3];
    const float* offs    = (const float*)d_in[4];
    const float* emb     = (const float*)d_in[5];
    const float* filt_W  = (const float*)d_in[6];
    const float* filt_b  = (const float*)d_in[7];
    const float* int_W1  = (const float*)d_in[8];
    const float* int_b1  = (const float*)d_in[9];
    const float* int_W2  = (const float*)d_in[10];
    const float* int_b2  = (const float*)d_in[11];
    const float* mix_Wmu = (const float*)d_in[12];
    const float* mix_W1  = (const float*)d_in[13];
    const float* mix_b1  = (const float*)d_in[14];
    const float* mix_W2  = (const float*)d_in[15];
    const float* mix_b2  = (const float*)d_in[16];
    float* out = (float*)d_out;

    void *p_q, *p_mu, *p_h, *p_x, *p_mumix, *p_ctx, *p_hm, *p_xm, *p_wH, *p_wL;
    cudaGetSymbolAddress(&p_q, g_q);
    cudaGetSymbolAddress(&p_mu, g_mu);
    cudaGetSymbolAddress(&p_h, g_h);
    cudaGetSymbolAddress(&p_x, g_x);
    cudaGetSymbolAddress(&p_mumix, g_mumix);
    cudaGetSymbolAddress(&p_ctx, g_ctx);
    cudaGetSymbolAddress(&p_hm, g_hm);
    cudaGetSymbolAddress(&p_xm, g_xm);
    cudaGetSymbolAddress(&p_wH, g_wH);
    cudaGetSymbolAddress(&p_wL, g_wL);

    // precompute: geometry, table, init, ALL weight transposes (one launch)
    edge_geom<<<(N_EDGES + 255) / 256, 256>>>(R, idx_i, idx_j, offs);
    build_table<<<NTAB, F3>>>(filt_W, filt_b);
    init_atoms<<<N_ATOMS, 128>>>(Z, emb);
    transpose_all<<<dim3(192, 15), 256>>>(int_W1, int_W2, mix_Wmu, mix_W1, mix_W2);

    const __nv_bfloat16* wH = (const __nv_bfloat16*)p_wH;
    const __nv_bfloat16* wL = (const __nv_bfloat16*)p_wL;

    auto gemm = [&](const float* A, size_t woff, const float* bias, float* C,
                    int M, int N, int K, int act) {
        mma_gemm<<<dim3(N / 64, (M + 127) / 128), 256>>>(
            A, wH + woff, wL + woff, bias, C, M, N, K, act);
    };

    for (int it = 0; it < 3; ++it) {
        size_t wb = (size_t)it * WT_PER_ITER;
        gemm((const float*)p_q, wb + 0,
             int_b1 + (long)it * F_DIM, (float*)p_h, N_ATOMS, F_DIM, F_DIM, 1);
        gemm((const float*)p_h, wb + 16384,
             int_b2 + (long)it * F3, (float*)p_x, N_ATOMS, F3, F_DIM, 0);

        edge_message<<<(N_EDGES + EPB - 1) / EPB, 128>>>(idx_i, idx_j);
        apply_deltas<<<N_ATOMS, 128>>>();

        gemm((const float*)p_mu, wb + 65536,
             nullptr, (float*)p_mumix, 3 * N_ATOMS, 2 * F_DIM, F_DIM, 0);
        ctx_kernel<<<N_ATOMS, 128>>>();
        gemm((const float*)p_ctx, wb + 98304,
             mix_b1 + (long)it * F_DIM, (float*)p_hm, N_ATOMS, F_DIM, 2 * F_DIM, 1);
        gemm((const float*)p_hm, wb + 131072,
             mix_b2 + (long)it * F3, (float*)p_xm, N_ATOMS, F3, F_DIM, 0);
        mix_update<<<N_ATOMS, 128>>>();
    }

    cudaMemcpyAsync(out, p_q, (size_t)N_ATOMS * F_DIM * sizeof(float),
                    cudaMemcpyDeviceToDevice);
    cudaMemcpyAsync(out + (size_t)N_ATOMS * F_DIM, p_mu,
                    (size_t)N_ATOMS * 3 * F_DIM * sizeof(float),
                    cudaMemcpyDeviceToDevice);
}